// round 1
// baseline (speedup 1.0000x reference)
#include <cuda_runtime.h>

#define B_TOTAL 262144
#define IN_DIM 28
#define HID 128
#define LAT 64
#define NCODES 512

#define GRID1 148
#define WARPS1 12
#define THREADS1 (WARPS1 * 32)
#define ROWB 4
#define TOTWARPS (GRID1 * WARPS1)

// ---- K1 shared-memory layout (floats) ----
#define OF_W1   0
#define OF_B1   (OF_W1 + IN_DIM * HID)        // 3584
#define OF_W2   (OF_B1 + HID)                 // 3712
#define OF_B2   (OF_W2 + HID * LAT)           // 11904
#define OF_CBT  (OF_B2 + LAT)                 // 11968  (k-major codebook [k*512+c])
#define OF_E2   (OF_CBT + LAT * NCODES)       // 44736
#define OF_SCR1 (OF_E2 + NCODES)              // 45248
#define WSCR1   (ROWB * IN_DIM + ROWB * HID + ROWB * LAT)  // 880 per warp
#define SMEM1_FLOATS (OF_SCR1 + WARPS1 * WSCR1)
#define SMEM1_BYTES  (SMEM1_FLOATS * 4)

// ---- K2 shared-memory layout (floats) ----
#define OF_DW1  0
#define OF_DB1  (OF_DW1 + LAT * HID)          // 8192
#define OF_DW2  (OF_DB1 + HID)                // 8320
#define OF_DB2  (OF_DW2 + HID * IN_DIM)       // 11904
#define OF_CB2  (OF_DB2 + IN_DIM)             // 11932 (row-major codebook)
#define OF_SCR2 (OF_CB2 + NCODES * LAT)       // 44700
#define WSCR2   (ROWB * LAT + ROWB * HID)     // 768 per warp
#define SMEM2_FLOATS (OF_SCR2 + WARPS1 * WSCR2)
#define SMEM2_BYTES  (SMEM2_FLOATS * 4)

__device__ int   g_idx[B_TOTAL];
__device__ float g_vq_part[GRID1];
__device__ float g_rec_part[GRID1];

// ============================================================================
// K1: encoder (x -> h -> z), nearest-code argmin, vq-loss partials
// ============================================================================
__global__ void __launch_bounds__(THREADS1, 1)
k_encode(const float* __restrict__ x,
         const float* __restrict__ w1, const float* __restrict__ b1,
         const float* __restrict__ w2, const float* __restrict__ b2,
         const float* __restrict__ cb)
{
    extern __shared__ float sm[];
    float* s_w1  = sm + OF_W1;
    float* s_b1  = sm + OF_B1;
    float* s_w2  = sm + OF_W2;
    float* s_b2  = sm + OF_B2;
    float* s_cbt = sm + OF_CBT;
    float* s_e2  = sm + OF_E2;

    const int tid = threadIdx.x;

    for (int i = tid; i < IN_DIM * HID; i += THREADS1) s_w1[i] = w1[i];
    for (int i = tid; i < HID;          i += THREADS1) s_b1[i] = b1[i];
    for (int i = tid; i < HID * LAT;    i += THREADS1) s_w2[i] = w2[i];
    for (int i = tid; i < LAT;          i += THREADS1) s_b2[i] = b2[i];
    // codebook transposed to k-major for conflict-free distance loop
    for (int i = tid; i < NCODES * LAT; i += THREADS1) {
        int c = i / LAT, k = i % LAT;
        s_cbt[k * NCODES + c] = cb[i];
    }
    for (int c = tid; c < NCODES; c += THREADS1) {
        float s = 0.f;
        for (int k = 0; k < LAT; k++) { float v = cb[c * LAT + k]; s = fmaf(v, v, s); }
        s_e2[c] = s;
    }
    __syncthreads();

    const int warp = tid >> 5, lane = tid & 31;
    float* xs = sm + OF_SCR1 + warp * WSCR1;     // [ROWB][28]
    float* hs = xs + ROWB * IN_DIM;              // [ROWB][128]
    float* zs = hs + ROWB * HID;                 // [ROWB][64]

    const unsigned FULL = 0xffffffffu;
    float vq_local = 0.f;
    const int gw = blockIdx.x * WARPS1 + warp;

    for (int base = gw * ROWB; base < B_TOTAL; base += TOTWARPS * ROWB) {
        // --- load x tile ---
        const float* xg = x + (long)base * IN_DIM;
        for (int i = lane; i < ROWB * IN_DIM; i += 32) xs[i] = xg[i];
        __syncwarp();

        // --- phase B: h = relu(x @ W1 + b1) ---
        {
            float acc[ROWB][4];
            #pragma unroll
            for (int r = 0; r < ROWB; r++)
                #pragma unroll
                for (int jj = 0; jj < 4; jj++) acc[r][jj] = s_b1[lane + 32 * jj];
            #pragma unroll 4
            for (int k = 0; k < IN_DIM; k++) {
                float wv[4];
                #pragma unroll
                for (int jj = 0; jj < 4; jj++) wv[jj] = s_w1[k * HID + lane + 32 * jj];
                #pragma unroll
                for (int r = 0; r < ROWB; r++) {
                    float xv = xs[r * IN_DIM + k];
                    #pragma unroll
                    for (int jj = 0; jj < 4; jj++) acc[r][jj] = fmaf(xv, wv[jj], acc[r][jj]);
                }
            }
            #pragma unroll
            for (int r = 0; r < ROWB; r++)
                #pragma unroll
                for (int jj = 0; jj < 4; jj++)
                    hs[r * HID + lane + 32 * jj] = fmaxf(acc[r][jj], 0.f);
        }
        __syncwarp();

        // --- phase C: z = h @ W2 + b2 ---
        {
            float acc[ROWB][2];
            #pragma unroll
            for (int r = 0; r < ROWB; r++) {
                acc[r][0] = s_b2[lane];
                acc[r][1] = s_b2[lane + 32];
            }
            #pragma unroll 4
            for (int k = 0; k < HID; k++) {
                float w0 = s_w2[k * LAT + lane];
                float w1v = s_w2[k * LAT + lane + 32];
                #pragma unroll
                for (int r = 0; r < ROWB; r++) {
                    float hv = hs[r * HID + k];
                    acc[r][0] = fmaf(hv, w0,  acc[r][0]);
                    acc[r][1] = fmaf(hv, w1v, acc[r][1]);
                }
            }
            #pragma unroll
            for (int r = 0; r < ROWB; r++) {
                zs[r * LAT + lane]      = acc[r][0];
                zs[r * LAT + lane + 32] = acc[r][1];
            }
        }
        __syncwarp();

        // --- phase D: distances + argmin (||e||^2 - 2 z.e; ||z||^2 is row-const) ---
        float minv[ROWB];
        int   mini[ROWB];
        #pragma unroll
        for (int r = 0; r < ROWB; r++) { minv[r] = 3.4e38f; mini[r] = 0; }

        #pragma unroll
        for (int cc = 0; cc < 4; cc++) {
            float dacc[ROWB][4];
            #pragma unroll
            for (int r = 0; r < ROWB; r++)
                #pragma unroll
                for (int u = 0; u < 4; u++) dacc[r][u] = 0.f;
            const int c0 = lane + 128 * cc;
            #pragma unroll 4
            for (int k = 0; k < LAT; k++) {
                float cv[4];
                #pragma unroll
                for (int u = 0; u < 4; u++) cv[u] = s_cbt[k * NCODES + c0 + 32 * u];
                #pragma unroll
                for (int r = 0; r < ROWB; r++) {
                    float zv = zs[r * LAT + k];
                    #pragma unroll
                    for (int u = 0; u < 4; u++) dacc[r][u] = fmaf(zv, cv[u], dacc[r][u]);
                }
            }
            #pragma unroll
            for (int u = 0; u < 4; u++) {
                int c = c0 + 32 * u;
                float e = s_e2[c];
                #pragma unroll
                for (int r = 0; r < ROWB; r++) {
                    float d = fmaf(-2.f, dacc[r][u], e);
                    if (d < minv[r]) { minv[r] = d; mini[r] = c; }
                }
            }
        }

        // warp argmin reduce (first-occurrence tie-break: smaller index)
        #pragma unroll
        for (int r = 0; r < ROWB; r++) {
            float mv = minv[r]; int mi = mini[r];
            #pragma unroll
            for (int off = 16; off; off >>= 1) {
                float ov = __shfl_down_sync(FULL, mv, off);
                int   oi = __shfl_down_sync(FULL, mi, off);
                if (ov < mv || (ov == mv && oi < mi)) { mv = ov; mi = oi; }
            }
            mini[r] = __shfl_sync(FULL, mi, 0);
        }
        if (lane == 0) {
            #pragma unroll
            for (int r = 0; r < ROWB; r++) g_idx[base + r] = mini[r];
        }

        // vq loss partial: sum (z - q)^2
        #pragma unroll
        for (int r = 0; r < ROWB; r++) {
            int mi = mini[r];
            #pragma unroll
            for (int jj = 0; jj < 2; jj++) {
                int k = lane + 32 * jj;
                float d = zs[r * LAT + k] - s_cbt[k * NCODES + mi];
                vq_local = fmaf(d, d, vq_local);
            }
        }
    }

    // block reduce vq_local
    #pragma unroll
    for (int off = 16; off; off >>= 1) vq_local += __shfl_down_sync(FULL, vq_local, off);
    __syncthreads();              // weights no longer needed; reuse smem
    if (lane == 0) sm[warp] = vq_local;
    __syncthreads();
    if (tid == 0) {
        float s = 0.f;
        for (int w = 0; w < WARPS1; w++) s += sm[w];
        g_vq_part[blockIdx.x] = s;
    }
}

// ============================================================================
// K2: decoder (q -> hd -> recon), recon write + recon-loss partials
// ============================================================================
__global__ void __launch_bounds__(THREADS1, 1)
k_decode(const float* __restrict__ x, const float* __restrict__ cb,
         const float* __restrict__ dw1, const float* __restrict__ db1,
         const float* __restrict__ dw2, const float* __restrict__ db2,
         float* __restrict__ out)
{
    extern __shared__ float sm[];
    float* s_w1 = sm + OF_DW1;
    float* s_b1 = sm + OF_DB1;
    float* s_w2 = sm + OF_DW2;
    float* s_b2 = sm + OF_DB2;
    float* s_cb = sm + OF_CB2;

    const int tid = threadIdx.x;
    for (int i = tid; i < LAT * HID;    i += THREADS1) s_w1[i] = dw1[i];
    for (int i = tid; i < HID;          i += THREADS1) s_b1[i] = db1[i];
    for (int i = tid; i < HID * IN_DIM; i += THREADS1) s_w2[i] = dw2[i];
    for (int i = tid; i < IN_DIM;       i += THREADS1) s_b2[i] = db2[i];
    for (int i = tid; i < NCODES * LAT; i += THREADS1) s_cb[i] = cb[i];
    __syncthreads();

    const int warp = tid >> 5, lane = tid & 31;
    float* qs  = sm + OF_SCR2 + warp * WSCR2;   // [ROWB][64]
    float* hds = qs + ROWB * LAT;               // [ROWB][128]

    const unsigned FULL = 0xffffffffu;
    float rec_local = 0.f;
    const int gw = blockIdx.x * WARPS1 + warp;

    for (int base = gw * ROWB; base < B_TOTAL; base += TOTWARPS * ROWB) {
        // --- gather quantized rows ---
        int idx4[ROWB];
        #pragma unroll
        for (int r = 0; r < ROWB; r++) idx4[r] = g_idx[base + r];
        #pragma unroll
        for (int r = 0; r < ROWB; r++) {
            qs[r * LAT + lane]      = s_cb[idx4[r] * LAT + lane];
            qs[r * LAT + lane + 32] = s_cb[idx4[r] * LAT + lane + 32];
        }
        __syncwarp();

        // --- hd = relu(q @ dW1 + db1) ---
        {
            float acc[ROWB][4];
            #pragma unroll
            for (int r = 0; r < ROWB; r++)
                #pragma unroll
                for (int jj = 0; jj < 4; jj++) acc[r][jj] = s_b1[lane + 32 * jj];
            #pragma unroll 4
            for (int k = 0; k < LAT; k++) {
                float wv[4];
                #pragma unroll
                for (int jj = 0; jj < 4; jj++) wv[jj] = s_w1[k * HID + lane + 32 * jj];
                #pragma unroll
                for (int r = 0; r < ROWB; r++) {
                    float qv = qs[r * LAT + k];
                    #pragma unroll
                    for (int jj = 0; jj < 4; jj++) acc[r][jj] = fmaf(qv, wv[jj], acc[r][jj]);
                }
            }
            #pragma unroll
            for (int r = 0; r < ROWB; r++)
                #pragma unroll
                for (int jj = 0; jj < 4; jj++)
                    hds[r * HID + lane + 32 * jj] = fmaxf(acc[r][jj], 0.f);
        }
        __syncwarp();

        // --- recon = hd @ dW2 + db2, write + loss ---
        if (lane < IN_DIM) {
            float acc[ROWB];
            #pragma unroll
            for (int r = 0; r < ROWB; r++) acc[r] = s_b2[lane];
            #pragma unroll 4
            for (int k = 0; k < HID; k++) {
                float wv = s_w2[k * IN_DIM + lane];
                #pragma unroll
                for (int r = 0; r < ROWB; r++) acc[r] = fmaf(hds[r * HID + k], wv, acc[r]);
            }
            #pragma unroll
            for (int r = 0; r < ROWB; r++) {
                long o = (long)(base + r) * IN_DIM + lane;
                out[o] = acc[r];
                float d = acc[r] - x[o];
                rec_local = fmaf(d, d, rec_local);
            }
        }
    }

    #pragma unroll
    for (int off = 16; off; off >>= 1) rec_local += __shfl_down_sync(FULL, rec_local, off);
    __syncthreads();
    if (lane == 0) sm[warp] = rec_local;
    __syncthreads();
    if (tid == 0) {
        float s = 0.f;
        for (int w = 0; w < WARPS1; w++) s += sm[w];
        g_rec_part[blockIdx.x] = s;
    }
}

// ============================================================================
// K3: finalize scalar losses
// ============================================================================
__global__ void k_final(float* __restrict__ out)
{
    if (threadIdx.x == 0) {
        double vs = 0.0, rs = 0.0;
        for (int i = 0; i < GRID1; i++) { vs += (double)g_vq_part[i]; rs += (double)g_rec_part[i]; }
        out[(long)B_TOTAL * IN_DIM]     = (float)(rs / ((double)B_TOTAL * IN_DIM));
        out[(long)B_TOTAL * IN_DIM + 1] = (float)(1.25 * vs / ((double)B_TOTAL * LAT));
    }
}

// ============================================================================
extern "C" void kernel_launch(void* const* d_in, const int* in_sizes, int n_in,
                              void* d_out, int out_size)
{
    const float* x    = (const float*)d_in[0];
    const float* ew1  = (const float*)d_in[1];
    const float* eb1  = (const float*)d_in[2];
    const float* ew2  = (const float*)d_in[3];
    const float* eb2  = (const float*)d_in[4];
    const float* cb   = (const float*)d_in[5];
    const float* dw1  = (const float*)d_in[6];
    const float* db1  = (const float*)d_in[7];
    const float* dw2  = (const float*)d_in[8];
    const float* db2  = (const float*)d_in[9];
    float* out = (float*)d_out;

    cudaFuncSetAttribute(k_encode, cudaFuncAttributeMaxDynamicSharedMemorySize, SMEM1_BYTES);
    cudaFuncSetAttribute(k_decode, cudaFuncAttributeMaxDynamicSharedMemorySize, SMEM2_BYTES);

    k_encode<<<GRID1, THREADS1, SMEM1_BYTES>>>(x, ew1, eb1, ew2, eb2, cb);
    k_decode<<<GRID1, THREADS1, SMEM2_BYTES>>>(x, cb, dw1, db1, dw2, db2, out);
    k_final<<<1, 32>>>(out);
}